// round 11
// baseline (speedup 1.0000x reference)
#include <cuda_runtime.h>
#include <cstdint>

#define NUM_SUB 16
#define CBSZ    1024
#define SUBD    64
#define NTOK    16384
#define EMBD    1024
#define CHUNK   128
#define TILE_N  64
#define TPB     128
#define QELEMS  ((size_t)NTOK * EMBD)

// smem layout (float offsets)
#define SXT_OFF 0        // [64][68] x transposed, padded      (4352 floats)
#define SX2_OFF 4352     // [64] token ||x||^2                 (64)
#define SC2_OFF 4416     // [1024] codeword ||c||^2            (1024)
#define SCT_OFF 5440     // [64][128] codeword chunk transposed(8192 floats)
#define SMEM_FLOATS 13632
#define SMEM_BYTES  (SMEM_FLOATS * 4)   // 54528

// ---------- packed f32x2 helpers ----------
__device__ __forceinline__ unsigned long long pk2(float lo, float hi) {
    unsigned long long r;
    asm("mov.b64 %0, {%1, %2};" : "=l"(r) : "f"(lo), "f"(hi));
    return r;
}
__device__ __forceinline__ unsigned long long ffma2(unsigned long long a,
                                                    unsigned long long b,
                                                    unsigned long long c) {
    unsigned long long d;
    asm("fma.rn.f32x2 %0, %1, %2, %3;" : "=l"(d) : "l"(a), "l"(b), "l"(c));
    return d;
}
__device__ __forceinline__ void unpk2(unsigned long long a, float& lo, float& hi) {
    unsigned int l, h;
    asm("mov.b64 {%0, %1}, %2;" : "=r"(l), "=r"(h) : "l"(a));
    lo = __uint_as_float(l); hi = __uint_as_float(h);
}

// Exact XLA:GPU warp-row-reduce sum of squares (R8-proven; do not alter):
// leaf_t = rn(rn(v[t]^2) + rn(v[t+32]^2)); butterfly 16,8,4,2,1.
__device__ __forceinline__ float sumsq_xla64(const float* __restrict__ v) {
    float p[32];
#pragma unroll
    for (int t = 0; t < 32; t++)
        p[t] = __fadd_rn(__fmul_rn(v[t], v[t]),
                         __fmul_rn(v[t + 32], v[t + 32]));
#pragma unroll
    for (int off = 16; off >= 1; off >>= 1)
#pragma unroll 32
        for (int t = 0; t < off; t++)
            p[t] = __fadd_rn(p[t], p[t + off]);
    return p[0];
}

// out: [quantized 16777216 f32][indices 262144 f32]
__global__ __launch_bounds__(TPB, 3)
void pq_argmin_kernel(const float* __restrict__ emb,
                      const float* __restrict__ cb,
                      float*       __restrict__ out)
{
    extern __shared__ float sm[];
    float* sxt = sm + SXT_OFF;   // [64][68]
    float* sx2 = sm + SX2_OFF;   // [64]
    float* sc2 = sm + SC2_OFF;   // [1024]
    float* sct = sm + SCT_OFF;   // [64][128]
    // candidate merge buffers alias the chunk region (used after all chunks)
    float* sd  = sct;            // [64][16]
    int*   si  = (int*)(sct + 1024);  // [64][16]

    const int m       = blockIdx.y;
    const int tid     = threadIdx.x;
    const int tx      = tid & 7;      // codeword-group
    const int ty      = tid >> 3;     // token-group (4 tokens)
    const int tokBase = blockIdx.x * TILE_N;
    const float* cbm  = cb + (size_t)m * CBSZ * SUBD;

    // ---- 1. stage x transposed: sxt[dim][tok] ----
#pragma unroll
    for (int it = 0; it < 8; it++) {
        int idx = tid + it * TPB;       // 0..1023
        int i4  = idx & 15;             // float4 index along dim
        int tk  = idx >> 4;             // token 0..63
        float4 v = *(const float4*)(emb + (size_t)(tokBase + tk) * EMBD + m * SUBD + i4 * 4);
        sxt[(4 * i4 + 0) * 68 + tk] = v.x;
        sxt[(4 * i4 + 1) * 68 + tk] = v.y;
        sxt[(4 * i4 + 2) * 68 + tk] = v.z;
        sxt[(4 * i4 + 3) * 68 + tk] = v.w;
    }

    // ---- 2. x2 per token (threads < 64), exact XLA scheme ----
    if (tid < 64) {
        float xs[SUBD];
        const float4* p = (const float4*)(emb + (size_t)(tokBase + tid) * EMBD + m * SUBD);
#pragma unroll
        for (int i = 0; i < 16; i++) {
            float4 v = p[i];
            xs[4*i] = v.x; xs[4*i+1] = v.y; xs[4*i+2] = v.z; xs[4*i+3] = v.w;
        }
        sx2[tid] = sumsq_xla64(xs);
    }

    // ---- 3. c2 for all 1024 codewords, exact XLA scheme ----
    for (int k = tid; k < CBSZ; k += TPB) {
        float cv[SUBD];
        const float4* cr = (const float4*)(cbm + (size_t)k * SUBD);
#pragma unroll
        for (int i = 0; i < 16; i++) {
            float4 v = cr[i];
            cv[4*i] = v.x; cv[4*i+1] = v.y; cv[4*i+2] = v.z; cv[4*i+3] = v.w;
        }
        sc2[k] = sumsq_xla64(cv);
    }
    __syncthreads();

    // per-thread x2 for its 4 tokens
    float x2r[4];
#pragma unroll
    for (int t = 0; t < 4; t++) x2r[t] = sx2[ty * 4 + t];

    // per-token top-2 screen candidates
    float bd0[4], bd1[4];
    int   bi0[4], bi1[4];
#pragma unroll
    for (int t = 0; t < 4; t++) { bd0[t] = 3.4e38f; bd1[t] = 3.4e38f; bi0[t] = 0; bi1[t] = 0; }

    for (int c0 = 0; c0 < CBSZ; c0 += CHUNK) {
        __syncthreads();   // previous chunk fully consumed
        // stage chunk transposed: sct[dim][cw]
#pragma unroll 1
        for (int it = 0; it < 16; it++) {
            int idx = tid + it * TPB;    // 0..2047
            int cw  = idx & 127;
            int i4  = idx >> 7;          // 0..15
            float4 v = *(const float4*)(cbm + (size_t)(c0 + cw) * SUBD + i4 * 4);
            sct[(4 * i4 + 0) * 128 + cw] = v.x;
            sct[(4 * i4 + 1) * 128 + cw] = v.y;
            sct[(4 * i4 + 2) * 128 + cw] = v.z;
            sct[(4 * i4 + 3) * 128 + cw] = v.w;
        }
        __syncthreads();

        // ---- mainloop: 4 tokens x 16 codewords per thread ----
        unsigned long long acc[4][8];
#pragma unroll
        for (int t = 0; t < 4; t++)
#pragma unroll
            for (int p = 0; p < 8; p++) acc[t][p] = 0ull;

#pragma unroll 4
        for (int k = 0; k < SUBD; k++) {
            float4 xa = *(const float4*)&sxt[k * 68 + ty * 4];
            unsigned long long xd0 = pk2(xa.x, xa.x);
            unsigned long long xd1 = pk2(xa.y, xa.y);
            unsigned long long xd2 = pk2(xa.z, xa.z);
            unsigned long long xd3 = pk2(xa.w, xa.w);
#pragma unroll
            for (int j = 0; j < 4; j++) {
                ulonglong2 cp = *(const ulonglong2*)&sct[k * 128 + 4 * tx + 32 * j];
                acc[0][2*j]   = ffma2(xd0, cp.x, acc[0][2*j]);
                acc[0][2*j+1] = ffma2(xd0, cp.y, acc[0][2*j+1]);
                acc[1][2*j]   = ffma2(xd1, cp.x, acc[1][2*j]);
                acc[1][2*j+1] = ffma2(xd1, cp.y, acc[1][2*j+1]);
                acc[2][2*j]   = ffma2(xd2, cp.x, acc[2][2*j]);
                acc[2][2*j+1] = ffma2(xd2, cp.y, acc[2][2*j+1]);
                acc[3][2*j]   = ffma2(xd3, cp.x, acc[3][2*j]);
                acc[3][2*j+1] = ffma2(xd3, cp.y, acc[3][2*j+1]);
            }
        }

        // ---- epilogue: dist + top-2 update ----
#pragma unroll
        for (int t = 0; t < 4; t++) {
#pragma unroll
            for (int j = 0; j < 4; j++) {
#pragma unroll
                for (int h = 0; h < 2; h++) {
                    float dlo, dhi;
                    unpk2(acc[t][2*j + h], dlo, dhi);
                    int kw = c0 + 4 * tx + 32 * j + 2 * h;
                    float dA = __fadd_rn(__fsub_rn(x2r[t], __fmul_rn(2.0f, dlo)), sc2[kw]);
                    float dB = __fadd_rn(__fsub_rn(x2r[t], __fmul_rn(2.0f, dhi)), sc2[kw + 1]);
                    if (dA < bd1[t]) {
                        if (dA < bd0[t]) { bd1[t]=bd0[t]; bi1[t]=bi0[t]; bd0[t]=dA; bi0[t]=kw; }
                        else             { bd1[t]=dA; bi1[t]=kw; }
                    }
                    if (dB < bd1[t]) {
                        if (dB < bd0[t]) { bd1[t]=bd0[t]; bi1[t]=bi0[t]; bd0[t]=dB; bi0[t]=kw+1; }
                        else             { bd1[t]=dB; bi1[t]=kw+1; }
                    }
                }
            }
        }
    }

    // ---- merge candidates across tx threads ----
    __syncthreads();   // all sct reads done; safe to alias
#pragma unroll
    for (int t = 0; t < 4; t++) {
        int tok = ty * 4 + t;
        sd[tok * 16 + 2 * tx]     = bd0[t];
        sd[tok * 16 + 2 * tx + 1] = bd1[t];
        si[tok * 16 + 2 * tx]     = bi0[t];
        si[tok * 16 + 2 * tx + 1] = bi1[t];
    }
    __syncthreads();

    // ---- winner selection + exact rescore + output (thread per token) ----
    if (tid < 64) {
        int tok = tid;
        float d0 = 3.4e38f, d1s = 3.4e38f;
        int   k0 = 0x7fffffff;
#pragma unroll
        for (int i = 0; i < 16; i++) {
            float d = sd[tok * 16 + i];
            int  kk = si[tok * 16 + i];
            if (d < d0 || (d == d0 && kk < k0)) { d1s = d0; d0 = d; k0 = kk; }
            else if (d < d1s) d1s = d;
        }
        int win = k0;
        if (__fsub_rn(d1s, d0) < 1e-3f) {
            // exact rescore (R8 bit-scheme) of all candidates within band
            float xloc[SUBD];
#pragma unroll
            for (int d = 0; d < SUBD; d++) xloc[d] = sxt[d * 68 + tok];
            float x2e = sx2[tok];
            float bde = 3.4e38f; int bke = 0x7fffffff;
            float cut = __fadd_rn(d0, 1e-3f);
#pragma unroll 1
            for (int i = 0; i < 16; i++) {
                if (sd[tok * 16 + i] <= cut) {
                    int kk = si[tok * 16 + i];
                    const float4* cr = (const float4*)(cbm + (size_t)kk * SUBD);
                    float dot = 0.f;
#pragma unroll
                    for (int i2 = 0; i2 < 16; i2++) {
                        float4 c = cr[i2];
                        dot = __fmaf_rn(xloc[4*i2],     c.x, dot);
                        dot = __fmaf_rn(xloc[4*i2 + 1], c.y, dot);
                        dot = __fmaf_rn(xloc[4*i2 + 2], c.z, dot);
                        dot = __fmaf_rn(xloc[4*i2 + 3], c.w, dot);
                    }
                    float dist = __fadd_rn(__fsub_rn(x2e, __fmul_rn(2.0f, dot)), sc2[kk]);
                    if (dist < bde || (dist == bde && kk < bke)) { bde = dist; bke = kk; }
                }
            }
            win = bke;
        }
        // gather winner codeword + write outputs
        const float4* w = (const float4*)(cbm + (size_t)win * SUBD);
        float4* qo = (float4*)(out + (size_t)(tokBase + tok) * EMBD + m * SUBD);
#pragma unroll
        for (int i = 0; i < 16; i++) qo[i] = w[i];
        out[QELEMS + (size_t)(tokBase + tok) * NUM_SUB + m] = (float)win;
    }
}

extern "C" void kernel_launch(void* const* d_in, const int* in_sizes, int n_in,
                              void* d_out, int out_size)
{
    const float* emb = (const float*)d_in[0];  // [8,2048,1024] f32
    const float* cb  = (const float*)d_in[1];  // [16,1024,64]  f32
    cudaFuncSetAttribute(pq_argmin_kernel,
                         cudaFuncAttributeMaxDynamicSharedMemorySize, SMEM_BYTES);
    dim3 grid(NTOK / TILE_N, NUM_SUB);         // (256, 16)
    pq_argmin_kernel<<<grid, TPB, SMEM_BYTES>>>(emb, cb, (float*)d_out);
}

// round 12
// speedup vs baseline: 1.3292x; 1.3292x over previous
#include <cuda_runtime.h>
#include <cstdint>

#define NUM_SUB 16
#define CBSZ    1024
#define SUBD    64
#define NTOK    16384
#define EMBD    1024
#define TPB     128
#define QELEMS  ((size_t)NTOK * EMBD)

// smem byte offsets
#define SXT_B   0        // ull[32][128]  x packed pairs, dim-pair major  (32768 B)
#define SCC_B   32768    // chunk: 32 codewords x 64 floats               (8192 B)
#define SC2_B   40960    // float[1024]                                   (4096 B)
#define SX2_B   45056    // float[128]                                    (512 B)
#define SMEM_BYTES 45568
// candidate buffers alias the chunk region after the last chunk:
#define CD_B    32768    // float[128][8]
#define CI_B    36864    // int[128][8]

__device__ float g_c2[NUM_SUB * CBSZ];

// ---------- packed f32x2 helpers ----------
__device__ __forceinline__ unsigned long long pk2(float lo, float hi) {
    unsigned long long r;
    asm("mov.b64 %0, {%1, %2};" : "=l"(r) : "f"(lo), "f"(hi));
    return r;
}
__device__ __forceinline__ unsigned long long ffma2(unsigned long long a,
                                                    unsigned long long b,
                                                    unsigned long long c) {
    unsigned long long d;
    asm("fma.rn.f32x2 %0, %1, %2, %3;" : "=l"(d) : "l"(a), "l"(b), "l"(c));
    return d;
}
__device__ __forceinline__ void unpk2(unsigned long long a, float& lo, float& hi) {
    unsigned int l, h;
    asm("mov.b64 {%0, %1}, %2;" : "=r"(l), "=r"(h) : "l"(a));
    lo = __uint_as_float(l); hi = __uint_as_float(h);
}

// Exact XLA:GPU warp-row-reduce sum of squares (R8-proven; do not alter):
// leaf_t = rn(rn(v[t]^2) + rn(v[t+32]^2)); butterfly 16,8,4,2,1.
__device__ __forceinline__ float sumsq_xla64(const float* __restrict__ v) {
    float p[32];
#pragma unroll
    for (int t = 0; t < 32; t++)
        p[t] = __fadd_rn(__fmul_rn(v[t], v[t]),
                         __fmul_rn(v[t + 32], v[t + 32]));
#pragma unroll
    for (int off = 16; off >= 1; off >>= 1)
#pragma unroll 32
        for (int t = 0; t < off; t++)
            p[t] = __fadd_rn(p[t], p[t + off]);
    return p[0];
}

// ---- kernel A: precompute c2 once (exact XLA scheme) ----
__global__ void c2_kernel(const float* __restrict__ cb) {
    const int m = blockIdx.x;
    const int k = threadIdx.x;          // 1024 threads
    float cv[SUBD];
    const float4* cr = (const float4*)(cb + ((size_t)m * CBSZ + k) * SUBD);
#pragma unroll
    for (int i = 0; i < 16; i++) {
        float4 v = cr[i];
        cv[4*i] = v.x; cv[4*i+1] = v.y; cv[4*i+2] = v.z; cv[4*i+3] = v.w;
    }
    g_c2[m * CBSZ + k] = sumsq_xla64(cv);
}

// ---- kernel B: main. out: [quantized 16777216 f32][indices 262144 f32] ----
__global__ __launch_bounds__(TPB, 4)
void pq_main(const float* __restrict__ emb,
             const float* __restrict__ cb,
             float*       __restrict__ out)
{
    extern __shared__ char sm[];
    unsigned long long* sxt = (unsigned long long*)(sm + SXT_B); // [kp][tok]
    float*              scc = (float*)(sm + SCC_B);
    float*              sc2 = (float*)(sm + SC2_B);
    float*              sx2 = (float*)(sm + SX2_B);
    float*              cd  = (float*)(sm + CD_B);
    int*                ci  = (int*)(sm + CI_B);

    const int m       = blockIdx.y;
    const int tid     = threadIdx.x;
    const int lane    = tid & 31;
    const int w       = tid >> 5;
    const int tokBase = blockIdx.x * TPB;
    const float* cbm  = cb + (size_t)m * CBSZ * SUBD;

    // ---- stage my token: x2 (exact XLA) + packed pairs into sxt ----
    {
        float xs[SUBD];
        const float4* p = (const float4*)(emb + (size_t)(tokBase + tid) * EMBD + m * SUBD);
#pragma unroll
        for (int i = 0; i < 16; i++) {
            float4 v = p[i];
            xs[4*i] = v.x; xs[4*i+1] = v.y; xs[4*i+2] = v.z; xs[4*i+3] = v.w;
        }
        sx2[tid] = sumsq_xla64(xs);
#pragma unroll
        for (int kp = 0; kp < 32; kp++)
            sxt[kp * 128 + tid] = pk2(xs[2*kp], xs[2*kp+1]);
    }
    // ---- load precomputed c2 (coalesced) ----
#pragma unroll
    for (int i = 0; i < 8; i++)
        sc2[tid + i * TPB] = g_c2[m * CBSZ + tid + i * TPB];
    __syncthreads();

    float x2r[4];
#pragma unroll
    for (int t = 0; t < 4; t++) x2r[t] = sx2[lane + 32 * t];

    // per-token top-2 over this warp's codeword slices
    float bd0[4], bd1[4];
    int   bi0[4], bi1[4];
#pragma unroll
    for (int t = 0; t < 4; t++) { bd0[t]=3.4e38f; bd1[t]=3.4e38f; bi0[t]=0; bi1[t]=0; }

    for (int c0 = 0; c0 < CBSZ; c0 += 32) {
        __syncthreads();   // previous chunk consumed
        // stage 32 codewords: coalesced LDG.128 -> identity STS.128
#pragma unroll
        for (int it = 0; it < 4; it++) {
            int idx = tid + it * TPB;        // 0..511 float4s
            int cw  = idx >> 4;
            int i4  = idx & 15;
            ((float4*)scc)[idx] = *(const float4*)(cbm + (size_t)(c0 + cw) * SUBD + i4 * 4);
        }
        __syncthreads();

        // warp w handles codewords [c0+8w, c0+8w+8)
        const unsigned long long* ccw = (const unsigned long long*)scc + (w * 8) * 32;

        unsigned long long acc[4][8];
#pragma unroll
        for (int t = 0; t < 4; t++)
#pragma unroll
            for (int c = 0; c < 8; c++) acc[t][c] = 0ull;

#pragma unroll 4
        for (int kp = 0; kp < 32; kp++) {
            const unsigned long long* xrow = sxt + kp * 128;
            unsigned long long xd0 = xrow[lane];
            unsigned long long xd1 = xrow[lane + 32];
            unsigned long long xd2 = xrow[lane + 64];
            unsigned long long xd3 = xrow[lane + 96];
#pragma unroll
            for (int c = 0; c < 8; c++) {
                unsigned long long cc = ccw[c * 32 + kp];   // warp-uniform broadcast
                acc[0][c] = ffma2(xd0, cc, acc[0][c]);
                acc[1][c] = ffma2(xd1, cc, acc[1][c]);
                acc[2][c] = ffma2(xd2, cc, acc[2][c]);
                acc[3][c] = ffma2(xd3, cc, acc[3][c]);
            }
        }

        // epilogue: dist + top-2 (screen only; exact rescore later)
#pragma unroll
        for (int c = 0; c < 8; c++) {
            int   cw  = c0 + w * 8 + c;
            float c2v = sc2[cw];
#pragma unroll
            for (int t = 0; t < 4; t++) {
                float lo, hi;
                unpk2(acc[t][c], lo, hi);
                float dot  = __fadd_rn(lo, hi);
                float dist = __fadd_rn(__fsub_rn(x2r[t], __fmul_rn(2.0f, dot)), c2v);
                if (dist < bd1[t]) {
                    if (dist < bd0[t]) { bd1[t]=bd0[t]; bi1[t]=bi0[t]; bd0[t]=dist; bi0[t]=cw; }
                    else               { bd1[t]=dist; bi1[t]=cw; }
                }
            }
        }
    }

    // ---- merge candidates across 4 warps (alias chunk region) ----
    __syncthreads();
#pragma unroll
    for (int t = 0; t < 4; t++) {
        int tok = lane + 32 * t;
        cd[tok * 8 + 2 * w]     = bd0[t];
        cd[tok * 8 + 2 * w + 1] = bd1[t];
        ci[tok * 8 + 2 * w]     = bi0[t];
        ci[tok * 8 + 2 * w + 1] = bi1[t];
    }
    __syncthreads();

    // ---- per-token winner: merge 8 + margin-gated exact rescore (R8 scheme) ----
    {
        const int tok = tid;
        float d0 = 3.4e38f, d1 = 3.4e38f;
        int   k0 = 0x7fffffff;
#pragma unroll
        for (int i = 0; i < 8; i++) {
            float d = cd[tok * 8 + i];
            int  kk = ci[tok * 8 + i];
            if (d < d0 || (d == d0 && kk < k0)) { d1 = d0; d0 = d; k0 = kk; }
            else if (d < d1) d1 = d;
        }
        int win = k0;
        if (__fsub_rn(d1, d0) < 1e-3f) {
            float xloc[SUBD];
#pragma unroll
            for (int kp = 0; kp < 32; kp++)
                unpk2(sxt[kp * 128 + tok], xloc[2*kp], xloc[2*kp+1]);
            float x2e = sx2[tok];
            float bde = 3.4e38f; int bke = 0x7fffffff;
            float cut = __fadd_rn(d0, 1e-3f);
#pragma unroll 1
            for (int i = 0; i < 8; i++) {
                if (cd[tok * 8 + i] <= cut) {
                    int kk = ci[tok * 8 + i];
                    const float4* cr = (const float4*)(cbm + (size_t)kk * SUBD);
                    float dot = 0.f;
#pragma unroll
                    for (int i2 = 0; i2 < 16; i2++) {
                        float4 c = cr[i2];
                        dot = __fmaf_rn(xloc[4*i2],     c.x, dot);
                        dot = __fmaf_rn(xloc[4*i2 + 1], c.y, dot);
                        dot = __fmaf_rn(xloc[4*i2 + 2], c.z, dot);
                        dot = __fmaf_rn(xloc[4*i2 + 3], c.w, dot);
                    }
                    float dist = __fadd_rn(__fsub_rn(x2e, __fmul_rn(2.0f, dot)), sc2[kk]);
                    if (dist < bde || (dist == bde && kk < bke)) { bde = dist; bke = kk; }
                }
            }
            win = bke;
        }
        // gather winner + write outputs
        const float4* wv = (const float4*)(cbm + (size_t)win * SUBD);
        float4* qo = (float4*)(out + (size_t)(tokBase + tok) * EMBD + m * SUBD);
#pragma unroll
        for (int i = 0; i < 16; i++) qo[i] = wv[i];
        out[QELEMS + (size_t)(tokBase + tok) * NUM_SUB + m] = (float)win;
    }
}

extern "C" void kernel_launch(void* const* d_in, const int* in_sizes, int n_in,
                              void* d_out, int out_size)
{
    const float* emb = (const float*)d_in[0];  // [8,2048,1024] f32
    const float* cb  = (const float*)d_in[1];  // [16,1024,64]  f32

    c2_kernel<<<NUM_SUB, 1024>>>(cb);

    cudaFuncSetAttribute(pq_main,
                         cudaFuncAttributeMaxDynamicSharedMemorySize, SMEM_BYTES);
    dim3 grid(NTOK / TPB, NUM_SUB);            // (128, 16)
    pq_main<<<grid, TPB, SMEM_BYTES>>>(emb, cb, (float*)d_out);
}